// round 6
// baseline (speedup 1.0000x reference)
#include <cuda_runtime.h>
#include <cuda_bf16.h>

#define E_MAX   250000
#define A_MAX   10000
#define CHUNK   128     // edges staged per barrier round
#define UB      4       // edges per load-batch (MLP group)

// Scratch (no allocations allowed -> __device__ globals).
__device__ int g_count[A_MAX];
__device__ int g_offsets[A_MAX + 1];
__device__ int g_cursor[A_MAX];
__device__ int g_edge_order[E_MAX];

// ---------------------------------------------------------------------------
__global__ void count_kernel(const int* __restrict__ centers, int E) {
    int e = blockIdx.x * blockDim.x + threadIdx.x;
    if (e < E) atomicAdd(&g_count[centers[e]], 1);
}

// Single-block exclusive scan; writes cursors + sentinel, re-zeros g_count.
__global__ void scan_kernel(int nAtoms, int E) {
    __shared__ int part[1024];
    const int tid = threadIdx.x;
    const int chunk = (nAtoms + 1023) >> 10;
    const int b = tid * chunk;
    const int e = min(b + chunk, nAtoms);

    int cnt[32];
    int s = 0;
    for (int i = b; i < e; i++) { cnt[i - b] = g_count[i]; s += cnt[i - b]; }
    part[tid] = s;
    __syncthreads();
    for (int off = 1; off < 1024; off <<= 1) {
        int t = 0;
        if (tid >= off) t = part[tid - off];
        __syncthreads();
        part[tid] += t;
        __syncthreads();
    }
    int run = part[tid] - s;
    for (int i = b; i < e; i++) {
        g_offsets[i] = run;
        g_cursor[i]  = run;
        run += cnt[i - b];
        g_count[i] = 0;
    }
    if (tid == 1023) g_offsets[nAtoms] = E;
}

__global__ void scatter_kernel(const int* __restrict__ centers, int E) {
    int e = blockIdx.x * blockDim.x + threadIdx.x;
    if (e < E) {
        int c = centers[e];
        int p = atomicAdd(&g_cursor[c], 1);
        g_edge_order[p] = e;
    }
}

// ---------------------------------------------------------------------------
// s_sh layout per edge: 16 contiguous floats = 4 quads:
//   q0 = [sh0, sh1_0, sh1_1, sh1_2]
//   q1 = [sh2_0, sh2_1, sh2_2, sh2_3]
//   q2 = [sh2_4, sh3_0, sh3_1, sh3_2]
//   q3 = [sh3_3, sh3_4, sh3_5, sh3_6]

template<int L, int KL>
__device__ __forceinline__ void fma_edge(
    const float2 a, const float2 b, const int i,
    const float* __restrict__ s_shf, const float4* __restrict__ s_shq,
    float2* acc)
{
    constexpr int MC = 2 * L + 1;
    const float px = a.x * b.x;
    const float py = a.y * b.y;
    float sh[MC];
    if (L == 0) {
        sh[0] = s_shf[i * 16];
    } else if (L == 1) {
        const float4 q0 = s_shq[i * 4];
        sh[0] = q0.y; sh[1] = q0.z; sh[2] = q0.w;
    } else if (L == 2) {
        const float4 q1 = s_shq[i * 4 + 1];
        const float4 q2 = s_shq[i * 4 + 2];
        sh[0] = q1.x; sh[1] = q1.y; sh[2] = q1.z; sh[3] = q1.w; sh[4] = q2.x;
    } else {
        const float4 q2 = s_shq[i * 4 + 2];
        const float4 q3 = s_shq[i * 4 + 3];
        sh[0] = q2.y; sh[1] = q2.z; sh[2] = q2.w;
        sh[3] = q3.x; sh[4] = q3.y; sh[5] = q3.z; sh[6] = q3.w;
    }
    #pragma unroll
    for (int m = 0; m < MC; m++) {
        acc[m].x += sh[m] * px;
        acc[m].y += sh[m] * py;
    }
}

template<int L, int KL>
__device__ __forceinline__ void run_region(
    const int k,
    const float* __restrict__ rb, const float* __restrict__ emb,
    const int cnt, const int* __restrict__ el,
    const int* __restrict__ neighbors,
    const float* __restrict__ sh0, const float* __restrict__ sh1,
    const float* __restrict__ sh2, const float* __restrict__ sh3,
    float* __restrict__ outp,
    const int tid, int2* s_meta, float4* s_shq)
{
    constexpr int MC = 2 * L + 1;
    float2 acc[MC];
    #pragma unroll
    for (int m = 0; m < MC; m++) { acc[m].x = 0.f; acc[m].y = 0.f; }

    const float* s_shf = (const float*)s_shq;

    for (int base = 0; base < cnt; base += CHUNK) {
        const int n = min(CHUNK, cnt - base);

        // Stage meta + 16 sh floats per edge.
        for (int idx = tid; idx < n * 16; idx += 320) {
            const int i = idx >> 4;
            const int c = idx & 15;
            const int e = el[base + i];
            float v;
            if (c == 0)      { v = sh0[e]; s_meta[i] = make_int2(e, neighbors[e]); }
            else if (c < 4)  v = sh1[(long)e * 3 + (c - 1)];
            else if (c < 9)  v = sh2[(long)e * 5 + (c - 4)];
            else             v = sh3[(long)e * 7 + (c - 9)];
            ((float*)s_shq)[idx] = v;
        }
        __syncthreads();

        // Batched inner loop: issue all 2*UB independent LDG.64 first,
        // then consume. Keeps ~8 loads in flight per thread.
        int i = 0;
        for (; i + UB <= n; i += UB) {
            int2 me[UB];
            #pragma unroll
            for (int j = 0; j < UB; j++) me[j] = s_meta[i + j];
            float2 a[UB], b[UB];
            #pragma unroll
            for (int j = 0; j < UB; j++) {
                a[j] = *(const float2*)(rb  + (long)me[j].x * KL  + k);
                b[j] = *(const float2*)(emb + (long)me[j].y * 256 + k);
            }
            #pragma unroll
            for (int j = 0; j < UB; j++)
                fma_edge<L, KL>(a[j], b[j], i + j, s_shf, s_shq, acc);
        }
        for (; i < n; i++) {
            const int2 me = s_meta[i];
            const float2 a = *(const float2*)(rb  + (long)me.x * KL  + k);
            const float2 b = *(const float2*)(emb + (long)me.y * 256 + k);
            fma_edge<L, KL>(a, b, i, s_shf, s_shq, acc);
        }
        __syncthreads();
    }

    #pragma unroll
    for (int m = 0; m < MC; m++)
        *(float2*)(outp + (long)m * KL) = acc[m];
}

// One CTA per atom, 320 threads, warp-aligned l regions.
__global__ void __launch_bounds__(320)
density_kernel(const float* __restrict__ sh0, const float* __restrict__ sh1,
               const float* __restrict__ sh2, const float* __restrict__ sh3,
               const float* __restrict__ rb0, const float* __restrict__ rb1,
               const float* __restrict__ rb2, const float* __restrict__ rb3,
               const float* __restrict__ emb, const int* __restrict__ neighbors,
               float* __restrict__ out, int nAtoms)
{
    const int atom = blockIdx.x;
    const int tid  = threadIdx.x;

    __shared__ int2   s_meta[CHUNK];
    __shared__ float4 s_shq[CHUNK * 4];

    const long B1 = (long)nAtoms * 256;
    const long B2 = B1 + (long)nAtoms * 576;
    const long B3 = B2 + (long)nAtoms * 640;

    const int  start = g_offsets[atom];
    const int  cnt   = g_offsets[atom + 1] - start;
    const int* el    = g_edge_order + start;

    if (tid < 128) {
        const int k = tid * 2;
        run_region<0, 256>(k, rb0, emb, cnt, el, neighbors, sh0, sh1, sh2, sh3,
                           out + (long)atom * 256 + k, tid, s_meta, s_shq);
    } else if (tid < 224) {
        const int k = (tid - 128) * 2;
        run_region<1, 192>(k, rb1, emb, cnt, el, neighbors, sh0, sh1, sh2, sh3,
                           out + B1 + (long)atom * 576 + k, tid, s_meta, s_shq);
    } else if (tid < 288) {
        const int k = (tid - 224) * 2;
        run_region<2, 128>(k, rb2, emb, cnt, el, neighbors, sh0, sh1, sh2, sh3,
                           out + B2 + (long)atom * 640 + k, tid, s_meta, s_shq);
    } else {
        const int k = (tid - 288) * 2;
        run_region<3, 64>(k, rb3, emb, cnt, el, neighbors, sh0, sh1, sh2, sh3,
                           out + B3 + (long)atom * 448 + k, tid, s_meta, s_shq);
    }
}

// ---------------------------------------------------------------------------
extern "C" void kernel_launch(void* const* d_in, const int* in_sizes, int n_in,
                              void* d_out, int out_size)
{
    const float* sh[4];
    const float* rb[4];
    const bool interleaved = ((long)in_sizes[1] > (long)in_sizes[0] * 8);
    for (int l = 0; l < 4; l++) {
        if (interleaved) {
            sh[l] = (const float*)d_in[2 * l];
            rb[l] = (const float*)d_in[2 * l + 1];
        } else {
            sh[l] = (const float*)d_in[l];
            rb[l] = (const float*)d_in[4 + l];
        }
    }
    const float* emb       = (const float*)d_in[8];
    const int*   centers   = (const int*)d_in[9];
    const int*   neighbors = (const int*)d_in[10];
    float*       out       = (float*)d_out;

    const int E      = in_sizes[9];
    const int nAtoms = in_sizes[8] / 256;

    const int TB = 256;
    count_kernel  <<<(E + TB - 1) / TB, TB>>>(centers, E);
    scan_kernel   <<<1, 1024>>>(nAtoms, E);
    scatter_kernel<<<(E + TB - 1) / TB, TB>>>(centers, E);
    density_kernel<<<nAtoms, 320>>>(sh[0], sh[1], sh[2], sh[3],
                                    rb[0], rb[1], rb[2], rb[3],
                                    emb, neighbors, out, nAtoms);
}

// round 7
// speedup vs baseline: 1.1504x; 1.1504x over previous
#include <cuda_runtime.h>
#include <cuda_bf16.h>

#define E_MAX   250000
#define A_MAX   10000

// Scratch (no allocations allowed -> __device__ globals).
__device__ int    g_count[A_MAX];
__device__ int    g_offsets[A_MAX + 1];
__device__ int    g_cursor[A_MAX];
__device__ int2   g_meta[E_MAX];          // (edge, neighbor) in CSR order
__device__ float4 g_shq[E_MAX * 4];       // 16 sh floats per edge, CSR order

// ---------------------------------------------------------------------------
__global__ void count_kernel(const int* __restrict__ centers, int E) {
    int e = blockIdx.x * blockDim.x + threadIdx.x;
    if (e < E) atomicAdd(&g_count[centers[e]], 1);
}

// Single-block exclusive scan; writes cursors + sentinel, re-zeros g_count.
__global__ void scan_kernel(int nAtoms, int E) {
    __shared__ int part[1024];
    const int tid = threadIdx.x;
    const int chunk = (nAtoms + 1023) >> 10;
    const int b = tid * chunk;
    const int e = min(b + chunk, nAtoms);

    int cnt[32];
    int s = 0;
    for (int i = b; i < e; i++) { cnt[i - b] = g_count[i]; s += cnt[i - b]; }
    part[tid] = s;
    __syncthreads();
    for (int off = 1; off < 1024; off <<= 1) {
        int t = 0;
        if (tid >= off) t = part[tid - off];
        __syncthreads();
        part[tid] += t;
        __syncthreads();
    }
    int run = part[tid] - s;
    for (int i = b; i < e; i++) {
        g_offsets[i] = run;
        g_cursor[i]  = run;
        run += cnt[i - b];
        g_count[i] = 0;
    }
    if (tid == 1023) g_offsets[nAtoms] = E;
}

// Scatter + pack: build CSR edge list AND pre-stage everything the density
// kernel needs per edge (meta + all 16 sh values, quad layout):
//   q0 = [sh0, sh1_0, sh1_1, sh1_2]
//   q1 = [sh2_0, sh2_1, sh2_2, sh2_3]
//   q2 = [sh2_4, sh3_0, sh3_1, sh3_2]
//   q3 = [sh3_3, sh3_4, sh3_5, sh3_6]
// sh reads here are coalesced by e (native layout); writes are random 64B.
__global__ void scatter_pack_kernel(const int* __restrict__ centers,
                                    const int* __restrict__ neighbors,
                                    const float* __restrict__ sh0,
                                    const float* __restrict__ sh1,
                                    const float* __restrict__ sh2,
                                    const float* __restrict__ sh3,
                                    int E) {
    int e = blockIdx.x * blockDim.x + threadIdx.x;
    if (e >= E) return;
    const int c = centers[e];
    const int p = atomicAdd(&g_cursor[c], 1);
    g_meta[p] = make_int2(e, neighbors[e]);

    const float* s1 = sh1 + (long)e * 3;
    const float* s2 = sh2 + (long)e * 5;
    const float* s3 = sh3 + (long)e * 7;
    float4* dst = g_shq + (long)p * 4;
    dst[0] = make_float4(sh0[e], s1[0], s1[1], s1[2]);
    dst[1] = make_float4(s2[0], s2[1], s2[2], s2[3]);
    dst[2] = make_float4(s2[4], s3[0], s3[1], s3[2]);
    dst[3] = make_float4(s3[3], s3[4], s3[5], s3[6]);
}

// ---------------------------------------------------------------------------
// Density kernel: one CTA per atom, 320 threads, warp-aligned l regions:
//   t 0-127:   l0 (4 warps), k = 2t
//   t 128-223: l1 (3 warps), k = 2(t-128)
//   t 224-287: l2 (2 warps), k = 2(t-224)
//   t 288-319: l3 (1 warp),  k = 2(t-288)
// Barrier-free, SMEM-free: meta + sh come from CSR-ordered pre-staged arrays
// (uniform loads, L1-hot), rb/emb are coalesced LDG.64. All iterations
// independent -> deep MLP via unroll.

template<int L, int KL>
__device__ __forceinline__ void run_region(
    const int k,
    const float* __restrict__ rb, const float* __restrict__ emb,
    const int start, const int cnt,
    float* __restrict__ outp)
{
    constexpr int MC = 2 * L + 1;
    float2 acc[MC];
    #pragma unroll
    for (int m = 0; m < MC; m++) { acc[m].x = 0.f; acc[m].y = 0.f; }

    const int2*   __restrict__ meta = g_meta + start;
    const float4* __restrict__ shq  = g_shq + (long)start * 4;

    #pragma unroll 4
    for (int i = 0; i < cnt; i++) {
        const int2 me = __ldg(meta + i);
        const float2 a = *(const float2*)(rb  + (long)me.x * KL  + k);
        const float2 b = *(const float2*)(emb + (long)me.y * 256 + k);
        const float px = a.x * b.x;
        const float py = a.y * b.y;

        float sh[MC];
        if (L == 0) {
            sh[0] = __ldg((const float*)(shq + i * 4));
        } else if (L == 1) {
            const float4 q0 = __ldg(shq + i * 4);
            sh[0] = q0.y; sh[1] = q0.z; sh[2] = q0.w;
        } else if (L == 2) {
            const float4 q1 = __ldg(shq + i * 4 + 1);
            const float4 q2 = __ldg(shq + i * 4 + 2);
            sh[0] = q1.x; sh[1] = q1.y; sh[2] = q1.z; sh[3] = q1.w; sh[4] = q2.x;
        } else {
            const float4 q2 = __ldg(shq + i * 4 + 2);
            const float4 q3 = __ldg(shq + i * 4 + 3);
            sh[0] = q2.y; sh[1] = q2.z; sh[2] = q2.w;
            sh[3] = q3.x; sh[4] = q3.y; sh[5] = q3.z; sh[6] = q3.w;
        }

        #pragma unroll
        for (int m = 0; m < MC; m++) {
            acc[m].x += sh[m] * px;
            acc[m].y += sh[m] * py;
        }
    }

    #pragma unroll
    for (int m = 0; m < MC; m++)
        *(float2*)(outp + (long)m * KL) = acc[m];
}

__global__ void __launch_bounds__(320)
density_kernel(const float* __restrict__ rb0, const float* __restrict__ rb1,
               const float* __restrict__ rb2, const float* __restrict__ rb3,
               const float* __restrict__ emb,
               float* __restrict__ out, int nAtoms)
{
    const int atom = blockIdx.x;
    const int tid  = threadIdx.x;

    const long B1 = (long)nAtoms * 256;
    const long B2 = B1 + (long)nAtoms * 576;
    const long B3 = B2 + (long)nAtoms * 640;

    const int start = g_offsets[atom];
    const int cnt   = g_offsets[atom + 1] - start;

    if (tid < 128) {
        const int k = tid * 2;
        run_region<0, 256>(k, rb0, emb, start, cnt,
                           out + (long)atom * 256 + k);
    } else if (tid < 224) {
        const int k = (tid - 128) * 2;
        run_region<1, 192>(k, rb1, emb, start, cnt,
                           out + B1 + (long)atom * 576 + k);
    } else if (tid < 288) {
        const int k = (tid - 224) * 2;
        run_region<2, 128>(k, rb2, emb, start, cnt,
                           out + B2 + (long)atom * 640 + k);
    } else {
        const int k = (tid - 288) * 2;
        run_region<3, 64>(k, rb3, emb, start, cnt,
                           out + B3 + (long)atom * 448 + k);
    }
}

// ---------------------------------------------------------------------------
extern "C" void kernel_launch(void* const* d_in, const int* in_sizes, int n_in,
                              void* d_out, int out_size)
{
    const float* sh[4];
    const float* rb[4];
    const bool interleaved = ((long)in_sizes[1] > (long)in_sizes[0] * 8);
    for (int l = 0; l < 4; l++) {
        if (interleaved) {
            sh[l] = (const float*)d_in[2 * l];
            rb[l] = (const float*)d_in[2 * l + 1];
        } else {
            sh[l] = (const float*)d_in[l];
            rb[l] = (const float*)d_in[4 + l];
        }
    }
    const float* emb       = (const float*)d_in[8];
    const int*   centers   = (const int*)d_in[9];
    const int*   neighbors = (const int*)d_in[10];
    float*       out       = (float*)d_out;

    const int E      = in_sizes[9];
    const int nAtoms = in_sizes[8] / 256;

    const int TB = 256;
    count_kernel       <<<(E + TB - 1) / TB, TB>>>(centers, E);
    scan_kernel        <<<1, 1024>>>(nAtoms, E);
    scatter_pack_kernel<<<(E + TB - 1) / TB, TB>>>(centers, neighbors,
                                                   sh[0], sh[1], sh[2], sh[3], E);
    density_kernel     <<<nAtoms, 320>>>(rb[0], rb[1], rb[2], rb[3],
                                         emb, out, nAtoms);
}

// round 8
// speedup vs baseline: 1.4754x; 1.2825x over previous
#include <cuda_runtime.h>
#include <cuda_bf16.h>

#define E_MAX   250000
#define A_MAX   10000

// Scratch (no allocations allowed -> __device__ globals).
__device__ int    g_count[A_MAX];
__device__ int    g_offsets[A_MAX + 1];
__device__ int    g_cursor[A_MAX];
__device__ int2   g_meta[E_MAX];          // (edge, neighbor) in CSR order
__device__ float4 g_shq[E_MAX * 4];       // 16 sh floats per edge, CSR order

// ---------------------------------------------------------------------------
__global__ void count_kernel(const int* __restrict__ centers, int E) {
    int e = blockIdx.x * blockDim.x + threadIdx.x;
    if (e < E) atomicAdd(&g_count[centers[e]], 1);
}

__global__ void scan_kernel(int nAtoms, int E) {
    __shared__ int part[1024];
    const int tid = threadIdx.x;
    const int chunk = (nAtoms + 1023) >> 10;
    const int b = tid * chunk;
    const int e = min(b + chunk, nAtoms);

    int cnt[32];
    int s = 0;
    for (int i = b; i < e; i++) { cnt[i - b] = g_count[i]; s += cnt[i - b]; }
    part[tid] = s;
    __syncthreads();
    for (int off = 1; off < 1024; off <<= 1) {
        int t = 0;
        if (tid >= off) t = part[tid - off];
        __syncthreads();
        part[tid] += t;
        __syncthreads();
    }
    int run = part[tid] - s;
    for (int i = b; i < e; i++) {
        g_offsets[i] = run;
        g_cursor[i]  = run;
        run += cnt[i - b];
        g_count[i] = 0;
    }
    if (tid == 1023) g_offsets[nAtoms] = E;
}

// Scatter + pack: CSR edge list + pre-staged per-edge data.
//   q0 = [sh0, sh1_0, sh1_1, sh1_2]
//   q1 = [sh2_0, sh2_1, sh2_2, sh2_3]
//   q2 = [sh2_4, sh3_0, sh3_1, sh3_2]
//   q3 = [sh3_3, sh3_4, sh3_5, sh3_6]
__global__ void scatter_pack_kernel(const int* __restrict__ centers,
                                    const int* __restrict__ neighbors,
                                    const float* __restrict__ sh0,
                                    const float* __restrict__ sh1,
                                    const float* __restrict__ sh2,
                                    const float* __restrict__ sh3,
                                    int E) {
    int e = blockIdx.x * blockDim.x + threadIdx.x;
    if (e >= E) return;
    const int c = centers[e];
    const int p = atomicAdd(&g_cursor[c], 1);
    g_meta[p] = make_int2(e, neighbors[e]);

    const float* s1 = sh1 + (long)e * 3;
    const float* s2 = sh2 + (long)e * 5;
    const float* s3 = sh3 + (long)e * 7;
    float4* dst = g_shq + (long)p * 4;
    dst[0] = make_float4(sh0[e], s1[0], s1[1], s1[2]);
    dst[1] = make_float4(s2[0], s2[1], s2[2], s2[3]);
    dst[2] = make_float4(s2[4], s3[0], s3[1], s3[2]);
    dst[3] = make_float4(s3[3], s3[4], s3[5], s3[6]);
}

// ---------------------------------------------------------------------------
// sh extraction per l (from the pre-staged quads)
template<int L>
__device__ __forceinline__ void load_sh(const float4* __restrict__ shq,
                                        const int i, float* sh)
{
    if (L == 0) {
        sh[0] = __ldg((const float*)(shq + i * 4));
    } else if (L == 1) {
        const float4 q0 = __ldg(shq + i * 4);
        sh[0] = q0.y; sh[1] = q0.z; sh[2] = q0.w;
    } else if (L == 2) {
        const float4 q1 = __ldg(shq + i * 4 + 1);
        const float4 q2 = __ldg(shq + i * 4 + 2);
        sh[0] = q1.x; sh[1] = q1.y; sh[2] = q1.z; sh[3] = q1.w; sh[4] = q2.x;
    } else {
        const float4 q2 = __ldg(shq + i * 4 + 2);
        const float4 q3 = __ldg(shq + i * 4 + 3);
        sh[0] = q2.y; sh[1] = q2.z; sh[2] = q2.w;
        sh[3] = q3.x; sh[4] = q3.y; sh[5] = q3.z; sh[6] = q3.w;
    }
}

// float2-wide worker (2 k-channels), unroll 4 for small MC / 2 for large.
template<int L, int KL, int UNROLL>
__device__ __forceinline__ void run_region2(
    const int k, const float* __restrict__ rb, const float* __restrict__ emb,
    const int start, const int cnt, float* __restrict__ outp)
{
    constexpr int MC = 2 * L + 1;
    float2 acc[MC];
    #pragma unroll
    for (int m = 0; m < MC; m++) { acc[m].x = 0.f; acc[m].y = 0.f; }

    const int2*   __restrict__ meta = g_meta + start;
    const float4* __restrict__ shq  = g_shq + (long)start * 4;

    #pragma unroll 2
    for (int i = 0; i < cnt; i++) {
        const int2 me = __ldg(meta + i);
        const float2 a = *(const float2*)(rb  + (long)me.x * KL  + k);
        const float2 b = *(const float2*)(emb + (long)me.y * 256 + k);
        const float px = a.x * b.x;
        const float py = a.y * b.y;
        float sh[MC];
        load_sh<L>(shq, i, sh);
        #pragma unroll
        for (int m = 0; m < MC; m++) {
            acc[m].x += sh[m] * px;
            acc[m].y += sh[m] * py;
        }
    }
    #pragma unroll
    for (int m = 0; m < MC; m++)
        *(float2*)(outp + (long)m * KL) = acc[m];
}

// float4-wide worker (4 k-channels).
template<int L, int KL, int UNROLL>
__device__ __forceinline__ void run_region4(
    const int k, const float* __restrict__ rb, const float* __restrict__ emb,
    const int start, const int cnt, float* __restrict__ outp)
{
    constexpr int MC = 2 * L + 1;
    float4 acc[MC];
    #pragma unroll
    for (int m = 0; m < MC; m++) acc[m] = make_float4(0.f, 0.f, 0.f, 0.f);

    const int2*   __restrict__ meta = g_meta + start;
    const float4* __restrict__ shq  = g_shq + (long)start * 4;

    #pragma unroll 2
    for (int i = 0; i < cnt; i++) {
        const int2 me = __ldg(meta + i);
        const float4 a = *(const float4*)(rb  + (long)me.x * KL  + k);
        const float4 b = *(const float4*)(emb + (long)me.y * 256 + k);
        const float px = a.x * b.x;
        const float py = a.y * b.y;
        const float pz = a.z * b.z;
        const float pw = a.w * b.w;
        float sh[MC];
        load_sh<L>(shq, i, sh);
        #pragma unroll
        for (int m = 0; m < MC; m++) {
            acc[m].x += sh[m] * px;
            acc[m].y += sh[m] * py;
            acc[m].z += sh[m] * pz;
            acc[m].w += sh[m] * pw;
        }
    }
    #pragma unroll
    for (int m = 0; m < MC; m++)
        *(float4*)(outp + (long)m * KL) = acc[m];
}

// One CTA per atom, 224 threads (7 warps), warp-aligned l regions:
//   t 0-63   (w0-1): l0, float4, k = 4t        (256 ch)
//   t 64-159 (w2-4): l1, float2, k = 2(t-64)   (192 ch)
//   t 160-191(w5)  : l2, float4, k = 4(t-160)  (128 ch)
//   t 192-223(w6)  : l3, float2, k = 2(t-192)  (64 ch)
__global__ void __launch_bounds__(224, 6)
density_kernel(const float* __restrict__ rb0, const float* __restrict__ rb1,
               const float* __restrict__ rb2, const float* __restrict__ rb3,
               const float* __restrict__ emb,
               float* __restrict__ out, int nAtoms)
{
    const int atom = blockIdx.x;
    const int tid  = threadIdx.x;

    const long B1 = (long)nAtoms * 256;
    const long B2 = B1 + (long)nAtoms * 576;
    const long B3 = B2 + (long)nAtoms * 640;

    const int start = g_offsets[atom];
    const int cnt   = g_offsets[atom + 1] - start;

    if (tid < 64) {
        const int k = tid * 4;
        run_region4<0, 256, 4>(k, rb0, emb, start, cnt,
                               out + (long)atom * 256 + k);
    } else if (tid < 160) {
        const int k = (tid - 64) * 2;
        run_region2<1, 192, 4>(k, rb1, emb, start, cnt,
                               out + B1 + (long)atom * 576 + k);
    } else if (tid < 192) {
        const int k = (tid - 160) * 4;
        run_region4<2, 128, 2>(k, rb2, emb, start, cnt,
                               out + B2 + (long)atom * 640 + k);
    } else {
        const int k = (tid - 192) * 2;
        run_region2<3, 64, 2>(k, rb3, emb, start, cnt,
                               out + B3 + (long)atom * 448 + k);
    }
}

// ---------------------------------------------------------------------------
extern "C" void kernel_launch(void* const* d_in, const int* in_sizes, int n_in,
                              void* d_out, int out_size)
{
    const float* sh[4];
    const float* rb[4];
    const bool interleaved = ((long)in_sizes[1] > (long)in_sizes[0] * 8);
    for (int l = 0; l < 4; l++) {
        if (interleaved) {
            sh[l] = (const float*)d_in[2 * l];
            rb[l] = (const float*)d_in[2 * l + 1];
        } else {
            sh[l] = (const float*)d_in[l];
            rb[l] = (const float*)d_in[4 + l];
        }
    }
    const float* emb       = (const float*)d_in[8];
    const int*   centers   = (const int*)d_in[9];
    const int*   neighbors = (const int*)d_in[10];
    float*       out       = (float*)d_out;

    const int E      = in_sizes[9];
    const int nAtoms = in_sizes[8] / 256;

    const int TB = 256;
    count_kernel       <<<(E + TB - 1) / TB, TB>>>(centers, E);
    scan_kernel        <<<1, 1024>>>(nAtoms, E);
    scatter_pack_kernel<<<(E + TB - 1) / TB, TB>>>(centers, neighbors,
                                                   sh[0], sh[1], sh[2], sh[3], E);
    density_kernel     <<<nAtoms, 224>>>(rb[0], rb[1], rb[2], rb[3],
                                         emb, out, nAtoms);
}

// round 9
// speedup vs baseline: 1.5243x; 1.0331x over previous
#include <cuda_runtime.h>
#include <cuda_bf16.h>

#define E_MAX   250000
#define A_MAX   10000

// Scratch (no allocations allowed -> __device__ globals).
__device__ int    g_count[A_MAX];
__device__ int    g_offsets[A_MAX + 1];
__device__ int    g_cursor[A_MAX];
__device__ int2   g_meta[E_MAX];          // (edge, neighbor) in CSR order
__device__ float4 g_shq[E_MAX * 4];       // 16 sh floats per edge, CSR order

// ---------------------------------------------------------------------------
__global__ void count_kernel(const int* __restrict__ centers, int E) {
    int e = blockIdx.x * blockDim.x + threadIdx.x;
    if (e < E) atomicAdd(&g_count[centers[e]], 1);
}

__global__ void scan_kernel(int nAtoms, int E) {
    __shared__ int part[1024];
    const int tid = threadIdx.x;
    const int chunk = (nAtoms + 1023) >> 10;
    const int b = tid * chunk;
    const int e = min(b + chunk, nAtoms);

    int cnt[32];
    int s = 0;
    for (int i = b; i < e; i++) { cnt[i - b] = g_count[i]; s += cnt[i - b]; }
    part[tid] = s;
    __syncthreads();
    for (int off = 1; off < 1024; off <<= 1) {
        int t = 0;
        if (tid >= off) t = part[tid - off];
        __syncthreads();
        part[tid] += t;
        __syncthreads();
    }
    int run = part[tid] - s;
    for (int i = b; i < e; i++) {
        g_offsets[i] = run;
        g_cursor[i]  = run;
        run += cnt[i - b];
        g_count[i] = 0;
    }
    if (tid == 1023) g_offsets[nAtoms] = E;
}

// Scatter + pack: CSR edge list + pre-staged per-edge data.
//   q0 = [sh0, sh1_0, sh1_1, sh1_2]
//   q1 = [sh2_0, sh2_1, sh2_2, sh2_3]
//   q2 = [sh2_4, sh3_0, sh3_1, sh3_2]
//   q3 = [sh3_3, sh3_4, sh3_5, sh3_6]
__global__ void scatter_pack_kernel(const int* __restrict__ centers,
                                    const int* __restrict__ neighbors,
                                    const float* __restrict__ sh0,
                                    const float* __restrict__ sh1,
                                    const float* __restrict__ sh2,
                                    const float* __restrict__ sh3,
                                    int E) {
    int e = blockIdx.x * blockDim.x + threadIdx.x;
    if (e >= E) return;
    const int c = centers[e];
    const int p = atomicAdd(&g_cursor[c], 1);
    g_meta[p] = make_int2(e, neighbors[e]);

    const float* s1 = sh1 + (long)e * 3;
    const float* s2 = sh2 + (long)e * 5;
    const float* s3 = sh3 + (long)e * 7;
    float4* dst = g_shq + (long)p * 4;
    dst[0] = make_float4(sh0[e], s1[0], s1[1], s1[2]);
    dst[1] = make_float4(s2[0], s2[1], s2[2], s2[3]);
    dst[2] = make_float4(s2[4], s3[0], s3[1], s3[2]);
    dst[3] = make_float4(s3[3], s3[4], s3[5], s3[6]);
}

// ---------------------------------------------------------------------------
template<int L>
__device__ __forceinline__ void load_sh(const float4* __restrict__ shq,
                                        const int i, float* sh)
{
    if (L == 0) {
        sh[0] = __ldg((const float*)(shq + i * 4));
    } else if (L == 1) {
        const float4 q0 = __ldg(shq + i * 4);
        sh[0] = q0.y; sh[1] = q0.z; sh[2] = q0.w;
    } else if (L == 2) {
        const float4 q1 = __ldg(shq + i * 4 + 1);
        const float4 q2 = __ldg(shq + i * 4 + 2);
        sh[0] = q1.x; sh[1] = q1.y; sh[2] = q1.z; sh[3] = q1.w; sh[4] = q2.x;
    } else {
        const float4 q2 = __ldg(shq + i * 4 + 2);
        const float4 q3 = __ldg(shq + i * 4 + 3);
        sh[0] = q2.y; sh[1] = q2.z; sh[2] = q2.w;
        sh[3] = q3.x; sh[4] = q3.y; sh[5] = q3.z; sh[6] = q3.w;
    }
}

// float2-wide worker (2 k-channels).
template<int L, int KL>
__device__ __forceinline__ void run_region2(
    const int k, const float* __restrict__ rb, const float* __restrict__ emb,
    const int start, const int cnt, float* __restrict__ outp)
{
    constexpr int MC = 2 * L + 1;
    float2 acc[MC];
    #pragma unroll
    for (int m = 0; m < MC; m++) { acc[m].x = 0.f; acc[m].y = 0.f; }

    const int2*   __restrict__ meta = g_meta + start;
    const float4* __restrict__ shq  = g_shq + (long)start * 4;

    #pragma unroll 2
    for (int i = 0; i < cnt; i++) {
        const int2 me = __ldg(meta + i);
        const float2 a = *(const float2*)(rb  + (long)me.x * KL  + k);
        const float2 b = *(const float2*)(emb + (long)me.y * 256 + k);
        const float px = a.x * b.x;
        const float py = a.y * b.y;
        float sh[MC];
        load_sh<L>(shq, i, sh);
        #pragma unroll
        for (int m = 0; m < MC; m++) {
            acc[m].x += sh[m] * px;
            acc[m].y += sh[m] * py;
        }
    }
    #pragma unroll
    for (int m = 0; m < MC; m++)
        *(float2*)(outp + (long)m * KL) = acc[m];
}

// float4-wide worker (4 k-channels).
template<int L, int KL>
__device__ __forceinline__ void run_region4(
    const int k, const float* __restrict__ rb, const float* __restrict__ emb,
    const int start, const int cnt, float* __restrict__ outp)
{
    constexpr int MC = 2 * L + 1;
    float4 acc[MC];
    #pragma unroll
    for (int m = 0; m < MC; m++) acc[m] = make_float4(0.f, 0.f, 0.f, 0.f);

    const int2*   __restrict__ meta = g_meta + start;
    const float4* __restrict__ shq  = g_shq + (long)start * 4;

    #pragma unroll 2
    for (int i = 0; i < cnt; i++) {
        const int2 me = __ldg(meta + i);
        const float4 a = *(const float4*)(rb  + (long)me.x * KL  + k);
        const float4 b = *(const float4*)(emb + (long)me.y * 256 + k);
        const float px = a.x * b.x;
        const float py = a.y * b.y;
        const float pz = a.z * b.z;
        const float pw = a.w * b.w;
        float sh[MC];
        load_sh<L>(shq, i, sh);
        #pragma unroll
        for (int m = 0; m < MC; m++) {
            acc[m].x += sh[m] * px;
            acc[m].y += sh[m] * py;
            acc[m].z += sh[m] * pz;
            acc[m].w += sh[m] * pw;
        }
    }
    #pragma unroll
    for (int m = 0; m < MC; m++)
        *(float4*)(outp + (long)m * KL) = acc[m];
}

// One CTA per atom, 192 threads (6 warps), warp-aligned l regions:
//   t 0-63    (w0-1): l0, float4, k = 4t          (256 ch)
//   t 64-111  (w2-3): l1, float4, k = 4(t-64)     (192 ch; w3 half-active)
//   t 128-159 (w4)  : l2, float4, k = 4(t-128)    (128 ch)
//   t 160-191 (w5)  : l3, float2, k = 2(t-160)    (64 ch)
__global__ void __launch_bounds__(192, 8)
density_kernel(const float* __restrict__ rb0, const float* __restrict__ rb1,
               const float* __restrict__ rb2, const float* __restrict__ rb3,
               const float* __restrict__ emb,
               float* __restrict__ out, int nAtoms)
{
    const int atom = blockIdx.x;
    const int tid  = threadIdx.x;

    const long B1 = (long)nAtoms * 256;
    const long B2 = B1 + (long)nAtoms * 576;
    const long B3 = B2 + (long)nAtoms * 640;

    const int start = g_offsets[atom];
    const int cnt   = g_offsets[atom + 1] - start;

    if (tid < 64) {
        const int k = tid * 4;
        run_region4<0, 256>(k, rb0, emb, start, cnt,
                            out + (long)atom * 256 + k);
    } else if (tid < 128) {
        const int k = (tid - 64) * 4;
        if (k < 192)
            run_region4<1, 192>(k, rb1, emb, start, cnt,
                                out + B1 + (long)atom * 576 + k);
    } else if (tid < 160) {
        const int k = (tid - 128) * 4;
        run_region4<2, 128>(k, rb2, emb, start, cnt,
                            out + B2 + (long)atom * 640 + k);
    } else {
        const int k = (tid - 160) * 2;
        run_region2<3, 64>(k, rb3, emb, start, cnt,
                           out + B3 + (long)atom * 448 + k);
    }
}

// ---------------------------------------------------------------------------
extern "C" void kernel_launch(void* const* d_in, const int* in_sizes, int n_in,
                              void* d_out, int out_size)
{
    const float* sh[4];
    const float* rb[4];
    const bool interleaved = ((long)in_sizes[1] > (long)in_sizes[0] * 8);
    for (int l = 0; l < 4; l++) {
        if (interleaved) {
            sh[l] = (const float*)d_in[2 * l];
            rb[l] = (const float*)d_in[2 * l + 1];
        } else {
            sh[l] = (const float*)d_in[l];
            rb[l] = (const float*)d_in[4 + l];
        }
    }
    const float* emb       = (const float*)d_in[8];
    const int*   centers   = (const int*)d_in[9];
    const int*   neighbors = (const int*)d_in[10];
    float*       out       = (float*)d_out;

    const int E      = in_sizes[9];
    const int nAtoms = in_sizes[8] / 256;

    const int TB = 256;
    count_kernel       <<<(E + TB - 1) / TB, TB>>>(centers, E);
    scan_kernel        <<<1, 1024>>>(nAtoms, E);
    scatter_pack_kernel<<<(E + TB - 1) / TB, TB>>>(centers, neighbors,
                                                   sh[0], sh[1], sh[2], sh[3], E);
    density_kernel     <<<nAtoms, 192>>>(rb[0], rb[1], rb[2], rb[3],
                                         emb, out, nAtoms);
}